// round 12
// baseline (speedup 1.0000x reference)
#include <cuda_runtime.h>
#include <cuda_fp16.h>
#include <math.h>
#include <stdint.h>

#define BB    64
#define INS   10000
#define EXPS  53
#define HID   1500
#define NC    2048
#define KX    1553
#define KXP   1664
#define S1    18
#define SPAN1 568           // 18*568 = 10224 >= 10000, mult of 8
#define S2    26
#define SPAN2 64            // 26*64 = 1664 exactly -> 1 chunk per block

#define FUSE1_VBLKS 104     // 104*256 threads * 4 j = BB*KXP exactly

// ---------------- device scratch ----------------
__device__ float g_part1[S1][BB][HID];
__device__ __align__(16) __half g_xh[BB * KXP];
__device__ float g_part2[S2][BB][NC];
__device__ float g_cmax[32][NC];
__device__ float g_cmaxF[NC];

__device__ __forceinline__ uint32_t smem_u32(const void* p) {
    uint32_t a;
    asm("{ .reg .u64 t; cvta.to.shared.u64 t, %1; cvt.u32.u64 %0, t; }" : "=r"(a) : "l"(p));
    return a;
}
#define LDX4(r, addr)                                                        \
    asm volatile("ldmatrix.sync.aligned.m8n8.x4.shared.b16 {%0,%1,%2,%3}, [%4];" \
        : "=r"((r)[0]), "=r"((r)[1]), "=r"((r)[2]), "=r"((r)[3]) : "r"(addr))
#define LDX4T(r, addr)                                                       \
    asm volatile("ldmatrix.sync.aligned.m8n8.x4.trans.shared.b16 {%0,%1,%2,%3}, [%4];" \
        : "=r"((r)[0]), "=r"((r)[1]), "=r"((r)[2]), "=r"((r)[3]) : "r"(addr))
#define MMA16816(d, a, b)                                                    \
    asm volatile("mma.sync.aligned.m16n8k16.row.col.f32.f16.f16.f32 "       \
        "{%0,%1,%2,%3}, {%4,%5,%6,%7}, {%8,%9}, {%0,%1,%2,%3};"              \
        : "+f"((d)[0]), "+f"((d)[1]), "+f"((d)[2]), "+f"((d)[3])             \
        : "r"((a)[0]), "r"((a)[1]), "r"((a)[2]), "r"((a)[3]),                \
          "r"((b)[0]), "r"((b)[1]))
__device__ __forceinline__ void cp16(uint32_t dst, const void* src, int src_bytes) {
    asm volatile("cp.async.cg.shared.global [%0], [%1], 16, %2;"
                 :: "r"(dst), "l"(src), "r"(src_bytes) : "memory");
}
#define CP_COMMIT()  asm volatile("cp.async.commit_group;" ::: "memory")
#define CP_WAIT(n)   asm volatile("cp.async.wait_group %0;" :: "n"(n) : "memory")

// ---------------------------------------------------------------------------
// HMMA fp16 split-K GEMM, templated on A dtype.
// Blocks with flat id >= ngemm do hpo column-max strips (GEMM1 launch only).
// ---------------------------------------------------------------------------
template<bool AF32>
__global__ __launch_bounds__(256, 2) void gemm_tpl(
    const void* __restrict__ Av, int KA,
    const float* __restrict__ W, int KB,
    float* __restrict__ part, int Nn, int span,
    int nbx, int ngemm, const float* __restrict__ hpo)
{
    const int tid = threadIdx.x;
    const int bid = blockIdx.x;
    if (bid >= ngemm) {                        // fused hpo colmax strips
        int cb = bid - ngemm;                  // 0..255
        int strip = cb >> 3;
        int j = (cb & 7) * 256 + tid;
        const float* col = hpo + (size_t)(strip * 64) * NC + j;
        float m = col[0];
        #pragma unroll 8
        for (int i = 1; i < 64; i++)
            m = fmaxf(m, col[(size_t)i * NC]);
        g_cmax[strip][j] = m;
        return;
    }

    constexpr int OFF_B = AF32 ? 17408 : 9216;
    constexpr int STG   = OFF_B + 33792;

    extern __shared__ __align__(16) char sm[];
    const int lane = tid & 31, w = tid >> 5;
    const int n0 = (bid % nbx) * 128;
    const int k0 = (bid / nbx) * span;
    const int kendA = min(k0 + span, KA);
    const int kendB = min(k0 + span, KB);
    const int nch = (kendA - k0 + 63) >> 6;
    const uint32_t sbase = smem_u32(sm);
    const int wm = (w & 1) * 32, wn = (w >> 1) * 32;

    float acc[2][4][4];
    #pragma unroll
    for (int i = 0; i < 2; i++)
        #pragma unroll
        for (int j = 0; j < 4; j++)
            #pragma unroll
            for (int e = 0; e < 4; e++) acc[i][j][e] = 0.f;

    const int aRow = lane & 15, aCol2 = (lane >> 4) * 16;   // bytes
    const int bRowT = lane & 15, bColT = (lane >> 4) * 8;
    const int bSeg = (w >> 1) * 128;
    const int cvRow = (tid >> 5) * 8 + (tid & 7);
    const int cvSeg = (tid >> 3) & 3;

    auto stage_cp = [&](int c) {
        const int kt = k0 + c * 64;
        const uint32_t sb = sbase + (uint32_t)(c & 1) * STG;
        if (AF32) {
            #pragma unroll
            for (int u = 0; u < 4; u++) {      // A fp32: 1024 granules
                int i = tid + u * 256;
                int m = i >> 4, g = i & 15;
                int gk = kt + g * 4;
                const float* src = (const float*)Av + (size_t)m * KA + gk;
                int ok = (gk + 4 <= kendA) ? 16 : 0;
                cp16(sb + (uint32_t)(m * 272 + g * 16), src, ok);
            }
        } else {
            #pragma unroll
            for (int u = 0; u < 2; u++) {      // A fp16: 512 granules
                int i = tid + u * 256;
                int m = i >> 3, g = i & 7;
                int gk = kt + g * 8;
                const __half* src = (const __half*)Av + (size_t)m * KA + gk;
                int ok = (gk + 8 <= kendA) ? 16 : 0;
                cp16(sb + (uint32_t)(m * 144 + g * 16), src, ok);
            }
        }
        #pragma unroll
        for (int u = 0; u < 8; u++) {          // B fp32: 2048 granules
            int j = tid + u * 256;
            int r = j >> 5, g = j & 31;
            int gk = kt + r, n = n0 + g * 4;
            const float* src = W + (size_t)gk * Nn + n;
            int ok = (gk < kendB && n + 4 <= Nn) ? 16 : 0;
            cp16(sb + OFF_B + (uint32_t)(r * 528 + g * 16), src, ok);
        }
        CP_COMMIT();
    };

    stage_cp(0);

    for (int c = 0; c < nch; c++) {
        if (c + 1 < nch) { stage_cp(c + 1); CP_WAIT(1); }
        else             { CP_WAIT(0); }
        __syncthreads();

        {   // ---- in-place converts
            char* stg = sm + (c & 1) * STG;
            if (AF32) {
                char* pa = stg + (tid & 63) * 272 + (tid >> 6) * 64;
                float4 va[4];
                #pragma unroll
                for (int i = 0; i < 4; i++) va[i] = *(const float4*)(pa + i * 16);
                uint4 oa[2];
                #pragma unroll
                for (int i = 0; i < 2; i++) {
                    __half2 h0 = __floats2half2_rn(va[2*i].x,   va[2*i].y);
                    __half2 h1 = __floats2half2_rn(va[2*i].z,   va[2*i].w);
                    __half2 h2 = __floats2half2_rn(va[2*i+1].x, va[2*i+1].y);
                    __half2 h3 = __floats2half2_rn(va[2*i+1].z, va[2*i+1].w);
                    oa[i] = make_uint4(*(uint32_t*)&h0, *(uint32_t*)&h1,
                                       *(uint32_t*)&h2, *(uint32_t*)&h3);
                }
                *(uint4*)(pa)      = oa[0];
                *(uint4*)(pa + 16) = oa[1];
            }
            char* pr = stg + OFF_B + cvRow * 528 + cvSeg * 128;
            float4 v[8];
            #pragma unroll
            for (int i = 0; i < 8; i++) v[i] = *(const float4*)(pr + i * 16);
            uint4 o[4];
            #pragma unroll
            for (int i = 0; i < 4; i++) {
                __half2 h0 = __floats2half2_rn(v[2*i].x,   v[2*i].y);
                __half2 h1 = __floats2half2_rn(v[2*i].z,   v[2*i].w);
                __half2 h2 = __floats2half2_rn(v[2*i+1].x, v[2*i+1].y);
                __half2 h3 = __floats2half2_rn(v[2*i+1].z, v[2*i+1].w);
                o[i] = make_uint4(*(uint32_t*)&h0, *(uint32_t*)&h1,
                                  *(uint32_t*)&h2, *(uint32_t*)&h3);
            }
            #pragma unroll
            for (int i = 0; i < 4; i++)
                *(uint4*)(pr + i * 16) = o[i];
        }
        __syncthreads();

        const uint32_t sb = sbase + (uint32_t)(c & 1) * STG;
        #pragma unroll
        for (int ks = 0; ks < 4; ks++) {
            uint32_t af[2][4], bf[2][4];
            #pragma unroll
            for (int mi = 0; mi < 2; mi++) {
                uint32_t ad = AF32
                    ? sb + (wm + mi * 16 + aRow) * 272 + ks * 64 + aCol2
                    : sb + (wm + mi * 16 + aRow) * 144 + ks * 32 + aCol2;
                LDX4(af[mi], ad);
            }
            #pragma unroll
            for (int p = 0; p < 2; p++)
                LDX4T(bf[p], sb + OFF_B + (ks * 16 + bRowT) * 528 + bSeg
                             + (p * 16 + bColT) * 2);
            #pragma unroll
            for (int mi = 0; mi < 2; mi++)
                #pragma unroll
                for (int ni = 0; ni < 4; ni++)
                    MMA16816(acc[mi][ni], af[mi], (&bf[ni >> 1][(ni & 1) * 2]));
        }
        __syncthreads();
    }

    float* pb = part + (size_t)(bid / nbx) * 64 * Nn;
    #pragma unroll
    for (int mi = 0; mi < 2; mi++)
        #pragma unroll
        for (int ni = 0; ni < 4; ni++) {
            int r0 = wm + mi * 16 + (lane >> 2);
            int cc = n0 + wn + ni * 8 + (lane & 3) * 2;
            if (cc < Nn) {
                pb[r0 * Nn + cc] = acc[mi][ni][0];
                pb[(r0 + 8) * Nn + cc] = acc[mi][ni][2];
            }
            if (cc + 1 < Nn) {
                pb[r0 * Nn + cc + 1] = acc[mi][ni][1];
                pb[(r0 + 8) * Nn + cc + 1] = acc[mi][ni][3];
            }
        }
}

// ---- fuse1 (vectorized): partials + bias + GELU + concat -> fp16
//      tail blocks: cmax strip collapse (float4)
__global__ void fuse1(const float* __restrict__ b1, const float* __restrict__ expx)
{
    int bx = blockIdx.x;
    if (bx >= FUSE1_VBLKS) {                   // 2 tail blocks: collapse strips
        int j4 = ((bx - FUSE1_VBLKS) * 256 + threadIdx.x) * 4;   // 0..2044
        float4 m = *(const float4*)&g_cmax[0][j4];
        #pragma unroll
        for (int p = 1; p < 32; p++) {
            float4 v = *(const float4*)&g_cmax[p][j4];
            m.x = fmaxf(m.x, v.x); m.y = fmaxf(m.y, v.y);
            m.z = fmaxf(m.z, v.z); m.w = fmaxf(m.w, v.w);
        }
        *(float4*)&g_cmaxF[j4] = m;
        return;
    }
    int g = bx * 256 + threadIdx.x;            // 0..26623
    int b = g / 416, r = g - b * 416;          // r: float4 group within row
    int n = r * 4;
    __half2 o01, o23;
    if (n + 4 <= HID) {                        // full GELU vector path
        float4 s = *(const float4*)&b1[n];
        #pragma unroll
        for (int p = 0; p < S1; p++) {
            float4 v = *(const float4*)&g_part1[p][b][n];
            s.x += v.x; s.y += v.y; s.z += v.z; s.w += v.w;
        }
        const float c = 0.70710678118654752f;
        s.x = 0.5f * s.x * (1.f + erff(s.x * c));
        s.y = 0.5f * s.y * (1.f + erff(s.y * c));
        s.z = 0.5f * s.z * (1.f + erff(s.z * c));
        s.w = 0.5f * s.w * (1.f + erff(s.w * c));
        o01 = __floats2half2_rn(s.x, s.y);
        o23 = __floats2half2_rn(s.z, s.w);
    } else {                                   // exp_x / zero region (n >= 1500)
        float e[4];
        #pragma unroll
        for (int i = 0; i < 4; i++) {
            int nn = n + i;
            e[i] = (nn < KX) ? expx[b * EXPS + (nn - HID)] : 0.f;
        }
        o01 = __floats2half2_rn(e[0], e[1]);
        o23 = __floats2half2_rn(e[2], e[3]);
    }
    *(uint32_t*)&g_xh[b * KXP + n]     = *(uint32_t*)&o01;
    *(uint32_t*)&g_xh[b * KXP + n + 2] = *(uint32_t*)&o23;
}

// ---- final (vectorized): out[b,j] = sigmoid(sum + b2[j]) * cmaxF[j]
__global__ void final_k(const float* __restrict__ b2, float* __restrict__ out)
{
    int g = blockIdx.x * 256 + threadIdx.x;    // 0..32767
    int b = g >> 9;                            // 512 j-groups per row
    int j4 = (g & 511) * 4;
    float4 m = *(const float4*)&g_cmaxF[j4];
    float4 s = *(const float4*)&b2[j4];
    #pragma unroll
    for (int p = 0; p < S2; p++) {
        float4 v = *(const float4*)&g_part2[p][b][j4];
        s.x += v.x; s.y += v.y; s.z += v.z; s.w += v.w;
    }
    float4 o;
    o.x = m.x / (1.f + expf(-s.x));
    o.y = m.y / (1.f + expf(-s.y));
    o.z = m.z / (1.f + expf(-s.z));
    o.w = m.w / (1.f + expf(-s.w));
    *(float4*)&out[b * NC + j4] = o;
}

// ---------------- launcher ----------------
extern "C" void kernel_launch(void* const* d_in, const int* in_sizes, int n_in,
                              void* d_out, int out_size)
{
    const float* gos  = (const float*)d_in[0];
    const float* expx = (const float*)d_in[1];
    const float* W1   = (const float*)d_in[2];
    const float* b1   = (const float*)d_in[3];
    const float* W2   = (const float*)d_in[4];
    const float* b2   = (const float*)d_in[5];
    const float* hpo  = (const float*)d_in[6];
    float* out = (float*)d_out;

    cudaFuncSetAttribute(gemm_tpl<true>,  cudaFuncAttributeMaxDynamicSharedMemorySize,
                         2 * (17408 + 33792));
    cudaFuncSetAttribute(gemm_tpl<false>, cudaFuncAttributeMaxDynamicSharedMemorySize,
                         2 * (9216 + 33792));

    __half* xh;
    float *p1, *p2;
    cudaGetSymbolAddress((void**)&xh, g_xh);
    cudaGetSymbolAddress((void**)&p1, g_part1);
    cudaGetSymbolAddress((void**)&p2, g_part2);

    // GEMM1 (A = raw fp32 gos) + fused hpo colmax strips
    gemm_tpl<true><<<12 * S1 + 256, 256, 2 * (17408 + 33792)>>>(
        gos, INS, W1, INS, p1, HID, SPAN1, 12, 12 * S1, hpo);

    // fuse1 (vectorized) + cmax strip collapse (2 tail blocks)
    fuse1<<<FUSE1_VBLKS + 2, 256>>>(b1, expx);

    // GEMM2 (A = fp16 g_xh): 416 single-chunk blocks
    gemm_tpl<false><<<16 * S2, 256, 2 * (9216 + 33792)>>>(
        xh, KXP, W2, KX, p2, NC, SPAN2, 16, 16 * S2, hpo);

    final_k<<<(BB * NC / 4) / 256, 256>>>(b2, out);
}

// round 13
// speedup vs baseline: 1.1558x; 1.1558x over previous
#include <cuda_runtime.h>
#include <cuda_fp16.h>
#include <math.h>
#include <stdint.h>

#define BB    64
#define INS   10000
#define EXPS  53
#define HID   1500
#define NC    2048
#define KX    1553
#define KXP   1664
#define S1    18
#define SPAN1 568           // 18*568 = 10224 >= 10000, mult of 8
#define S2    9
#define SPAN2 192           // 9*192 = 1728 >= 1664, mult of 8

#define FUSE1_BLKS ((BB * KXP) / 256)   // 416
#define ACC1_V     (BB * HID / 4)       // 24000 float4 groups
#define ACC2_V     (BB * NC / 4)        // 32768 float4 groups

// ---------------- device scratch ----------------
__device__ __align__(16) float g_acc1[BB * HID];
__device__ __align__(16) float g_acc2[BB * NC];
__device__ __align__(16) __half g_xh[BB * KXP];
__device__ float g_cmax[32][NC];
__device__ float g_cmaxF[NC];

__device__ __forceinline__ uint32_t smem_u32(const void* p) {
    uint32_t a;
    asm("{ .reg .u64 t; cvta.to.shared.u64 t, %1; cvt.u32.u64 %0, t; }" : "=r"(a) : "l"(p));
    return a;
}
#define LDX4(r, addr)                                                        \
    asm volatile("ldmatrix.sync.aligned.m8n8.x4.shared.b16 {%0,%1,%2,%3}, [%4];" \
        : "=r"((r)[0]), "=r"((r)[1]), "=r"((r)[2]), "=r"((r)[3]) : "r"(addr))
#define LDX4T(r, addr)                                                       \
    asm volatile("ldmatrix.sync.aligned.m8n8.x4.trans.shared.b16 {%0,%1,%2,%3}, [%4];" \
        : "=r"((r)[0]), "=r"((r)[1]), "=r"((r)[2]), "=r"((r)[3]) : "r"(addr))
#define MMA16816(d, a, b)                                                    \
    asm volatile("mma.sync.aligned.m16n8k16.row.col.f32.f16.f16.f32 "       \
        "{%0,%1,%2,%3}, {%4,%5,%6,%7}, {%8,%9}, {%0,%1,%2,%3};"              \
        : "+f"((d)[0]), "+f"((d)[1]), "+f"((d)[2]), "+f"((d)[3])             \
        : "r"((a)[0]), "r"((a)[1]), "r"((a)[2]), "r"((a)[3]),                \
          "r"((b)[0]), "r"((b)[1]))
__device__ __forceinline__ void cp16(uint32_t dst, const void* src, int src_bytes) {
    asm volatile("cp.async.cg.shared.global [%0], [%1], 16, %2;"
                 :: "r"(dst), "l"(src), "r"(src_bytes) : "memory");
}
#define CP_COMMIT()  asm volatile("cp.async.commit_group;" ::: "memory")
#define CP_WAIT(n)   asm volatile("cp.async.wait_group %0;" :: "n"(n) : "memory")

// ---------------- init: zero both accumulators (graph-replay safe) ---------
__global__ void init_acc()
{
    int g = blockIdx.x * 256 + threadIdx.x;
    if (g < ACC1_V) {
        *(float4*)&g_acc1[g * 4] = make_float4(0.f, 0.f, 0.f, 0.f);
    } else {
        int h = g - ACC1_V;
        if (h < ACC2_V)
            *(float4*)&g_acc2[h * 4] = make_float4(0.f, 0.f, 0.f, 0.f);
    }
}

// ---------------------------------------------------------------------------
// HMMA fp16 split-K GEMM, templated on A dtype. Epilogue: atomicAdd into acc.
// Blocks with flat id >= ngemm do hpo column-max strips (GEMM1 launch only).
// ---------------------------------------------------------------------------
template<bool AF32>
__global__ __launch_bounds__(256, 2) void gemm_tpl(
    const void* __restrict__ Av, int KA,
    const float* __restrict__ W, int KB,
    float* __restrict__ accOut, int Nn, int span,
    int nbx, int ngemm, const float* __restrict__ hpo)
{
    const int tid = threadIdx.x;
    const int bid = blockIdx.x;
    if (bid >= ngemm) {                        // fused hpo colmax strips
        int cb = bid - ngemm;                  // 0..255
        int strip = cb >> 3;
        int j = (cb & 7) * 256 + tid;
        const float* col = hpo + (size_t)(strip * 64) * NC + j;
        float m = col[0];
        #pragma unroll 8
        for (int i = 1; i < 64; i++)
            m = fmaxf(m, col[(size_t)i * NC]);
        g_cmax[strip][j] = m;
        return;
    }

    constexpr int OFF_B = AF32 ? 17408 : 9216;
    constexpr int STG   = OFF_B + 33792;

    extern __shared__ __align__(16) char sm[];
    const int lane = tid & 31, w = tid >> 5;
    const int n0 = (bid % nbx) * 128;
    const int k0 = (bid / nbx) * span;
    const int kendA = min(k0 + span, KA);
    const int kendB = min(k0 + span, KB);
    const int nch = (kendA - k0 + 63) >> 6;
    const uint32_t sbase = smem_u32(sm);
    const int wm = (w & 1) * 32, wn = (w >> 1) * 32;

    float acc[2][4][4];
    #pragma unroll
    for (int i = 0; i < 2; i++)
        #pragma unroll
        for (int j = 0; j < 4; j++)
            #pragma unroll
            for (int e = 0; e < 4; e++) acc[i][j][e] = 0.f;

    const int aRow = lane & 15, aCol2 = (lane >> 4) * 16;   // bytes
    const int bRowT = lane & 15, bColT = (lane >> 4) * 8;
    const int bSeg = (w >> 1) * 128;
    const int cvRow = (tid >> 5) * 8 + (tid & 7);
    const int cvSeg = (tid >> 3) & 3;

    auto stage_cp = [&](int c) {
        const int kt = k0 + c * 64;
        const uint32_t sb = sbase + (uint32_t)(c & 1) * STG;
        if (AF32) {
            #pragma unroll
            for (int u = 0; u < 4; u++) {      // A fp32: 1024 granules
                int i = tid + u * 256;
                int m = i >> 4, g = i & 15;
                int gk = kt + g * 4;
                const float* src = (const float*)Av + (size_t)m * KA + gk;
                int ok = (gk + 4 <= kendA) ? 16 : 0;
                cp16(sb + (uint32_t)(m * 272 + g * 16), src, ok);
            }
        } else {
            #pragma unroll
            for (int u = 0; u < 2; u++) {      // A fp16: 512 granules
                int i = tid + u * 256;
                int m = i >> 3, g = i & 7;
                int gk = kt + g * 8;
                const __half* src = (const __half*)Av + (size_t)m * KA + gk;
                int ok = (gk + 8 <= kendA) ? 16 : 0;
                cp16(sb + (uint32_t)(m * 144 + g * 16), src, ok);
            }
        }
        #pragma unroll
        for (int u = 0; u < 8; u++) {          // B fp32: 2048 granules
            int j = tid + u * 256;
            int r = j >> 5, g = j & 31;
            int gk = kt + r, n = n0 + g * 4;
            const float* src = W + (size_t)gk * Nn + n;
            int ok = (gk < kendB && n + 4 <= Nn) ? 16 : 0;
            cp16(sb + OFF_B + (uint32_t)(r * 528 + g * 16), src, ok);
        }
        CP_COMMIT();
    };

    stage_cp(0);

    for (int c = 0; c < nch; c++) {
        if (c + 1 < nch) { stage_cp(c + 1); CP_WAIT(1); }
        else             { CP_WAIT(0); }
        __syncthreads();

        {   // ---- in-place converts
            char* stg = sm + (c & 1) * STG;
            if (AF32) {
                char* pa = stg + (tid & 63) * 272 + (tid >> 6) * 64;
                float4 va[4];
                #pragma unroll
                for (int i = 0; i < 4; i++) va[i] = *(const float4*)(pa + i * 16);
                uint4 oa[2];
                #pragma unroll
                for (int i = 0; i < 2; i++) {
                    __half2 h0 = __floats2half2_rn(va[2*i].x,   va[2*i].y);
                    __half2 h1 = __floats2half2_rn(va[2*i].z,   va[2*i].w);
                    __half2 h2 = __floats2half2_rn(va[2*i+1].x, va[2*i+1].y);
                    __half2 h3 = __floats2half2_rn(va[2*i+1].z, va[2*i+1].w);
                    oa[i] = make_uint4(*(uint32_t*)&h0, *(uint32_t*)&h1,
                                       *(uint32_t*)&h2, *(uint32_t*)&h3);
                }
                *(uint4*)(pa)      = oa[0];
                *(uint4*)(pa + 16) = oa[1];
            }
            char* pr = stg + OFF_B + cvRow * 528 + cvSeg * 128;
            float4 v[8];
            #pragma unroll
            for (int i = 0; i < 8; i++) v[i] = *(const float4*)(pr + i * 16);
            uint4 o[4];
            #pragma unroll
            for (int i = 0; i < 4; i++) {
                __half2 h0 = __floats2half2_rn(v[2*i].x,   v[2*i].y);
                __half2 h1 = __floats2half2_rn(v[2*i].z,   v[2*i].w);
                __half2 h2 = __floats2half2_rn(v[2*i+1].x, v[2*i+1].y);
                __half2 h3 = __floats2half2_rn(v[2*i+1].z, v[2*i+1].w);
                o[i] = make_uint4(*(uint32_t*)&h0, *(uint32_t*)&h1,
                                  *(uint32_t*)&h2, *(uint32_t*)&h3);
            }
            #pragma unroll
            for (int i = 0; i < 4; i++)
                *(uint4*)(pr + i * 16) = o[i];
        }
        __syncthreads();

        const uint32_t sb = sbase + (uint32_t)(c & 1) * STG;
        #pragma unroll
        for (int ks = 0; ks < 4; ks++) {
            uint32_t af[2][4], bf[2][4];
            #pragma unroll
            for (int mi = 0; mi < 2; mi++) {
                uint32_t ad = AF32
                    ? sb + (wm + mi * 16 + aRow) * 272 + ks * 64 + aCol2
                    : sb + (wm + mi * 16 + aRow) * 144 + ks * 32 + aCol2;
                LDX4(af[mi], ad);
            }
            #pragma unroll
            for (int p = 0; p < 2; p++)
                LDX4T(bf[p], sb + OFF_B + (ks * 16 + bRowT) * 528 + bSeg
                             + (p * 16 + bColT) * 2);
            #pragma unroll
            for (int mi = 0; mi < 2; mi++)
                #pragma unroll
                for (int ni = 0; ni < 4; ni++)
                    MMA16816(acc[mi][ni], af[mi], (&bf[ni >> 1][(ni & 1) * 2]));
        }
        __syncthreads();
    }

    // ---- epilogue: atomic accumulate into global accumulator
    #pragma unroll
    for (int mi = 0; mi < 2; mi++)
        #pragma unroll
        for (int ni = 0; ni < 4; ni++) {
            int r0 = wm + mi * 16 + (lane >> 2);
            int cc = n0 + wn + ni * 8 + (lane & 3) * 2;
            if (cc < Nn) {
                atomicAdd(&accOut[r0 * Nn + cc],       acc[mi][ni][0]);
                atomicAdd(&accOut[(r0 + 8) * Nn + cc], acc[mi][ni][2]);
            }
            if (cc + 1 < Nn) {
                atomicAdd(&accOut[r0 * Nn + cc + 1],       acc[mi][ni][1]);
                atomicAdd(&accOut[(r0 + 8) * Nn + cc + 1], acc[mi][ni][3]);
            }
        }
}

// ---- fuse1: acc1 + bias + GELU + concat -> fp16 ; tail: cmax 32->1 --------
__global__ void fuse1(const float* __restrict__ b1, const float* __restrict__ expx)
{
    int bx = blockIdx.x;
    if (bx >= FUSE1_BLKS) {                    // 8 tail blocks: collapse strips
        int j = (bx - FUSE1_BLKS) * 256 + threadIdx.x;   // 0..2047
        float m = g_cmax[0][j];
        #pragma unroll
        for (int p = 1; p < 32; p++) m = fmaxf(m, g_cmax[p][j]);
        g_cmaxF[j] = m;
        return;
    }
    int idx = bx * 256 + threadIdx.x;
    int b = idx / KXP, n = idx - b * KXP;
    float v;
    if (n < HID) {
        float s = b1[n] + g_acc1[b * HID + n];
        v = 0.5f * s * (1.f + erff(s * 0.70710678118654752f));
    } else if (n < KX) {
        v = expx[b * EXPS + (n - HID)];
    } else {
        v = 0.f;
    }
    g_xh[idx] = __float2half(v);
}

// out[b,j] = sigmoid(acc2 + b2[j]) * cmaxF[j]  (exact factorization)
__global__ void final_k(const float* __restrict__ b2, float* __restrict__ out)
{
    int j = blockIdx.x * 256 + threadIdx.x;
    int b = blockIdx.y;
    float s = b2[j] + g_acc2[b * NC + j];
    out[b * NC + j] = g_cmaxF[j] / (1.f + expf(-s));
}

// ---------------- launcher ----------------
extern "C" void kernel_launch(void* const* d_in, const int* in_sizes, int n_in,
                              void* d_out, int out_size)
{
    const float* gos  = (const float*)d_in[0];
    const float* expx = (const float*)d_in[1];
    const float* W1   = (const float*)d_in[2];
    const float* b1   = (const float*)d_in[3];
    const float* W2   = (const float*)d_in[4];
    const float* b2   = (const float*)d_in[5];
    const float* hpo  = (const float*)d_in[6];
    float* out = (float*)d_out;

    cudaFuncSetAttribute(gemm_tpl<true>,  cudaFuncAttributeMaxDynamicSharedMemorySize,
                         2 * (17408 + 33792));
    cudaFuncSetAttribute(gemm_tpl<false>, cudaFuncAttributeMaxDynamicSharedMemorySize,
                         2 * (9216 + 33792));

    __half* xh;
    float *a1, *a2;
    cudaGetSymbolAddress((void**)&xh, g_xh);
    cudaGetSymbolAddress((void**)&a1, g_acc1);
    cudaGetSymbolAddress((void**)&a2, g_acc2);

    // zero accumulators (graph replay resets state)
    init_acc<<<(ACC1_V + ACC2_V + 255) / 256, 256>>>();

    // GEMM1 (A = raw fp32 gos) + fused hpo colmax strips
    gemm_tpl<true><<<12 * S1 + 256, 256, 2 * (17408 + 33792)>>>(
        gos, INS, W1, INS, a1, HID, SPAN1, 12, 12 * S1, hpo);

    // fuse1 + cmax strip collapse (8 tail blocks)
    fuse1<<<FUSE1_BLKS + 8, 256>>>(b1, expx);

    // GEMM2 (A = fp16 g_xh): 144 blocks, 3 chunks each
    gemm_tpl<false><<<16 * S2, 256, 2 * (9216 + 33792)>>>(
        xh, KXP, W2, KX, a2, NC, SPAN2, 16, 16 * S2, hpo);

    final_k<<<dim3(NC / 256, BB), 256>>>(b2, out);
}

// round 14
// speedup vs baseline: 1.1605x; 1.0041x over previous
#include <cuda_runtime.h>
#include <cuda_fp16.h>
#include <math.h>
#include <stdint.h>

#define BB    64
#define INS   10000
#define EXPS  53
#define HID   1500
#define NC    2048
#define KX    1553
#define KXP   1664
#define S1    24
#define SPAN1 424           // 24*424 = 10176 >= 10000, mult of 8
#define S2    26
#define SPAN2 64            // 26*64 = 1664 exactly -> single chunk per block

#define FUSE1_BLKS ((BB * KXP) / 256)   // 416
#define ACC1_V     (BB * HID / 4)       // 24000 float4 groups
#define ACC2_V     (BB * NC / 4)        // 32768 float4 groups -> 128 blocks

// ---------------- device scratch ----------------
__device__ __align__(16) float g_acc1[BB * HID];
__device__ __align__(16) float g_acc2[BB * NC];
__device__ __align__(16) __half g_xh[BB * KXP];
__device__ float g_cmax[32][NC];
__device__ float g_cmaxF[NC];

__device__ __forceinline__ uint32_t smem_u32(const void* p) {
    uint32_t a;
    asm("{ .reg .u64 t; cvta.to.shared.u64 t, %1; cvt.u32.u64 %0, t; }" : "=r"(a) : "l"(p));
    return a;
}
#define LDX4(r, addr)                                                        \
    asm volatile("ldmatrix.sync.aligned.m8n8.x4.shared.b16 {%0,%1,%2,%3}, [%4];" \
        : "=r"((r)[0]), "=r"((r)[1]), "=r"((r)[2]), "=r"((r)[3]) : "r"(addr))
#define LDX4T(r, addr)                                                       \
    asm volatile("ldmatrix.sync.aligned.m8n8.x4.trans.shared.b16 {%0,%1,%2,%3}, [%4];" \
        : "=r"((r)[0]), "=r"((r)[1]), "=r"((r)[2]), "=r"((r)[3]) : "r"(addr))
#define MMA16816(d, a, b)                                                    \
    asm volatile("mma.sync.aligned.m16n8k16.row.col.f32.f16.f16.f32 "       \
        "{%0,%1,%2,%3}, {%4,%5,%6,%7}, {%8,%9}, {%0,%1,%2,%3};"              \
        : "+f"((d)[0]), "+f"((d)[1]), "+f"((d)[2]), "+f"((d)[3])             \
        : "r"((a)[0]), "r"((a)[1]), "r"((a)[2]), "r"((a)[3]),                \
          "r"((b)[0]), "r"((b)[1]))
__device__ __forceinline__ void cp16(uint32_t dst, const void* src, int src_bytes) {
    asm volatile("cp.async.cg.shared.global [%0], [%1], 16, %2;"
                 :: "r"(dst), "l"(src), "r"(src_bytes) : "memory");
}
#define CP_COMMIT()  asm volatile("cp.async.commit_group;" ::: "memory")
#define CP_WAIT(n)   asm volatile("cp.async.wait_group %0;" :: "n"(n) : "memory")

// ---------------- init: zero acc1 only (acc2 zeroed in fuse1 tail) ---------
__global__ void init_acc()
{
    int g = blockIdx.x * 256 + threadIdx.x;
    if (g < ACC1_V)
        *(float4*)&g_acc1[g * 4] = make_float4(0.f, 0.f, 0.f, 0.f);
}

// ---------------------------------------------------------------------------
// HMMA fp16 split-K GEMM, templated on A dtype. Epilogue: atomicAdd into acc.
// Blocks with flat id >= ngemm do hpo column-max strips (GEMM1 launch only).
// ---------------------------------------------------------------------------
template<bool AF32>
__global__ __launch_bounds__(256, 2) void gemm_tpl(
    const void* __restrict__ Av, int KA,
    const float* __restrict__ W, int KB,
    float* __restrict__ accOut, int Nn, int span,
    int nbx, int ngemm, const float* __restrict__ hpo)
{
    const int tid = threadIdx.x;
    const int bid = blockIdx.x;
    if (bid >= ngemm) {                        // fused hpo colmax strips
        int cb = bid - ngemm;                  // 0..255
        int strip = cb >> 3;
        int j = (cb & 7) * 256 + tid;
        const float* col = hpo + (size_t)(strip * 64) * NC + j;
        float m = col[0];
        #pragma unroll 8
        for (int i = 1; i < 64; i++)
            m = fmaxf(m, col[(size_t)i * NC]);
        g_cmax[strip][j] = m;
        return;
    }

    constexpr int OFF_B = AF32 ? 17408 : 9216;
    constexpr int STG   = OFF_B + 33792;

    extern __shared__ __align__(16) char sm[];
    const int lane = tid & 31, w = tid >> 5;
    const int n0 = (bid % nbx) * 128;
    const int k0 = (bid / nbx) * span;
    const int kendA = min(k0 + span, KA);
    const int kendB = min(k0 + span, KB);
    const int nch = (kendA - k0 + 63) >> 6;
    const uint32_t sbase = smem_u32(sm);
    const int wm = (w & 1) * 32, wn = (w >> 1) * 32;

    float acc[2][4][4];
    #pragma unroll
    for (int i = 0; i < 2; i++)
        #pragma unroll
        for (int j = 0; j < 4; j++)
            #pragma unroll
            for (int e = 0; e < 4; e++) acc[i][j][e] = 0.f;

    const int aRow = lane & 15, aCol2 = (lane >> 4) * 16;   // bytes
    const int bRowT = lane & 15, bColT = (lane >> 4) * 8;
    const int bSeg = (w >> 1) * 128;
    const int cvRow = (tid >> 5) * 8 + (tid & 7);
    const int cvSeg = (tid >> 3) & 3;

    auto stage_cp = [&](int c) {
        const int kt = k0 + c * 64;
        const uint32_t sb = sbase + (uint32_t)(c & 1) * STG;
        if (AF32) {
            #pragma unroll
            for (int u = 0; u < 4; u++) {      // A fp32: 1024 granules
                int i = tid + u * 256;
                int m = i >> 4, g = i & 15;
                int gk = kt + g * 4;
                const float* src = (const float*)Av + (size_t)m * KA + gk;
                int ok = (gk + 4 <= kendA) ? 16 : 0;
                cp16(sb + (uint32_t)(m * 272 + g * 16), src, ok);
            }
        } else {
            #pragma unroll
            for (int u = 0; u < 2; u++) {      // A fp16: 512 granules
                int i = tid + u * 256;
                int m = i >> 3, g = i & 7;
                int gk = kt + g * 8;
                const __half* src = (const __half*)Av + (size_t)m * KA + gk;
                int ok = (gk + 8 <= kendA) ? 16 : 0;
                cp16(sb + (uint32_t)(m * 144 + g * 16), src, ok);
            }
        }
        #pragma unroll
        for (int u = 0; u < 8; u++) {          // B fp32: 2048 granules
            int j = tid + u * 256;
            int r = j >> 5, g = j & 31;
            int gk = kt + r, n = n0 + g * 4;
            const float* src = W + (size_t)gk * Nn + n;
            int ok = (gk < kendB && n + 4 <= Nn) ? 16 : 0;
            cp16(sb + OFF_B + (uint32_t)(r * 528 + g * 16), src, ok);
        }
        CP_COMMIT();
    };

    stage_cp(0);

    for (int c = 0; c < nch; c++) {
        if (c + 1 < nch) { stage_cp(c + 1); CP_WAIT(1); }
        else             { CP_WAIT(0); }
        __syncthreads();

        {   // ---- in-place converts
            char* stg = sm + (c & 1) * STG;
            if (AF32) {
                char* pa = stg + (tid & 63) * 272 + (tid >> 6) * 64;
                float4 va[4];
                #pragma unroll
                for (int i = 0; i < 4; i++) va[i] = *(const float4*)(pa + i * 16);
                uint4 oa[2];
                #pragma unroll
                for (int i = 0; i < 2; i++) {
                    __half2 h0 = __floats2half2_rn(va[2*i].x,   va[2*i].y);
                    __half2 h1 = __floats2half2_rn(va[2*i].z,   va[2*i].w);
                    __half2 h2 = __floats2half2_rn(va[2*i+1].x, va[2*i+1].y);
                    __half2 h3 = __floats2half2_rn(va[2*i+1].z, va[2*i+1].w);
                    oa[i] = make_uint4(*(uint32_t*)&h0, *(uint32_t*)&h1,
                                       *(uint32_t*)&h2, *(uint32_t*)&h3);
                }
                *(uint4*)(pa)      = oa[0];
                *(uint4*)(pa + 16) = oa[1];
            }
            char* pr = stg + OFF_B + cvRow * 528 + cvSeg * 128;
            float4 v[8];
            #pragma unroll
            for (int i = 0; i < 8; i++) v[i] = *(const float4*)(pr + i * 16);
            uint4 o[4];
            #pragma unroll
            for (int i = 0; i < 4; i++) {
                __half2 h0 = __floats2half2_rn(v[2*i].x,   v[2*i].y);
                __half2 h1 = __floats2half2_rn(v[2*i].z,   v[2*i].w);
                __half2 h2 = __floats2half2_rn(v[2*i+1].x, v[2*i+1].y);
                __half2 h3 = __floats2half2_rn(v[2*i+1].z, v[2*i+1].w);
                o[i] = make_uint4(*(uint32_t*)&h0, *(uint32_t*)&h1,
                                  *(uint32_t*)&h2, *(uint32_t*)&h3);
            }
            #pragma unroll
            for (int i = 0; i < 4; i++)
                *(uint4*)(pr + i * 16) = o[i];
        }
        __syncthreads();

        const uint32_t sb = sbase + (uint32_t)(c & 1) * STG;
        #pragma unroll
        for (int ks = 0; ks < 4; ks++) {
            uint32_t af[2][4], bf[2][4];
            #pragma unroll
            for (int mi = 0; mi < 2; mi++) {
                uint32_t ad = AF32
                    ? sb + (wm + mi * 16 + aRow) * 272 + ks * 64 + aCol2
                    : sb + (wm + mi * 16 + aRow) * 144 + ks * 32 + aCol2;
                LDX4(af[mi], ad);
            }
            #pragma unroll
            for (int p = 0; p < 2; p++)
                LDX4T(bf[p], sb + OFF_B + (ks * 16 + bRowT) * 528 + bSeg
                             + (p * 16 + bColT) * 2);
            #pragma unroll
            for (int mi = 0; mi < 2; mi++)
                #pragma unroll
                for (int ni = 0; ni < 4; ni++)
                    MMA16816(acc[mi][ni], af[mi], (&bf[ni >> 1][(ni & 1) * 2]));
        }
        __syncthreads();
    }

    // ---- epilogue: atomic accumulate into global accumulator
    #pragma unroll
    for (int mi = 0; mi < 2; mi++)
        #pragma unroll
        for (int ni = 0; ni < 4; ni++) {
            int r0 = wm + mi * 16 + (lane >> 2);
            int cc = n0 + wn + ni * 8 + (lane & 3) * 2;
            if (cc < Nn) {
                atomicAdd(&accOut[r0 * Nn + cc],       acc[mi][ni][0]);
                atomicAdd(&accOut[(r0 + 8) * Nn + cc], acc[mi][ni][2]);
            }
            if (cc + 1 < Nn) {
                atomicAdd(&accOut[r0 * Nn + cc + 1],       acc[mi][ni][1]);
                atomicAdd(&accOut[(r0 + 8) * Nn + cc + 1], acc[mi][ni][3]);
            }
        }
}

// ---- fuse1: acc1 + bias + GELU + concat -> fp16
//      tail blocks: cmax 32->1 collapse, then acc2 zeroing -------------------
__global__ void fuse1(const float* __restrict__ b1, const float* __restrict__ expx)
{
    int bx = blockIdx.x;
    if (bx >= FUSE1_BLKS + 8) {                // 128 tail blocks: zero acc2
        int h = (bx - FUSE1_BLKS - 8) * 256 + threadIdx.x;
        *(float4*)&g_acc2[h * 4] = make_float4(0.f, 0.f, 0.f, 0.f);
        return;
    }
    if (bx >= FUSE1_BLKS) {                    // 8 blocks: collapse cmax strips
        int j = (bx - FUSE1_BLKS) * 256 + threadIdx.x;   // 0..2047
        float m = g_cmax[0][j];
        #pragma unroll
        for (int p = 1; p < 32; p++) m = fmaxf(m, g_cmax[p][j]);
        g_cmaxF[j] = m;
        return;
    }
    int idx = bx * 256 + threadIdx.x;
    int b = idx / KXP, n = idx - b * KXP;
    float v;
    if (n < HID) {
        float s = b1[n] + g_acc1[b * HID + n];
        v = 0.5f * s * (1.f + erff(s * 0.70710678118654752f));
    } else if (n < KX) {
        v = expx[b * EXPS + (n - HID)];
    } else {
        v = 0.f;
    }
    g_xh[idx] = __float2half(v);
}

// out[b,j] = sigmoid(acc2 + b2[j]) * cmaxF[j]  (exact factorization)
__global__ void final_k(const float* __restrict__ b2, float* __restrict__ out)
{
    int j = blockIdx.x * 256 + threadIdx.x;
    int b = blockIdx.y;
    float s = b2[j] + g_acc2[b * NC + j];
    out[b * NC + j] = g_cmaxF[j] / (1.f + expf(-s));
}

// ---------------- launcher ----------------
extern "C" void kernel_launch(void* const* d_in, const int* in_sizes, int n_in,
                              void* d_out, int out_size)
{
    const float* gos  = (const float*)d_in[0];
    const float* expx = (const float*)d_in[1];
    const float* W1   = (const float*)d_in[2];
    const float* b1   = (const float*)d_in[3];
    const float* W2   = (const float*)d_in[4];
    const float* b2   = (const float*)d_in[5];
    const float* hpo  = (const float*)d_in[6];
    float* out = (float*)d_out;

    cudaFuncSetAttribute(gemm_tpl<true>,  cudaFuncAttributeMaxDynamicSharedMemorySize,
                         2 * (17408 + 33792));
    cudaFuncSetAttribute(gemm_tpl<false>, cudaFuncAttributeMaxDynamicSharedMemorySize,
                         2 * (9216 + 33792));

    __half* xh;
    float *a1, *a2;
    cudaGetSymbolAddress((void**)&xh, g_xh);
    cudaGetSymbolAddress((void**)&a1, g_acc1);
    cudaGetSymbolAddress((void**)&a2, g_acc2);

    // zero acc1 (acc2 zeroed inside fuse1, before GEMM2)
    init_acc<<<(ACC1_V + 255) / 256, 256>>>();

    // GEMM1 (A = raw fp32 gos) + fused hpo colmax strips: 288 + 256 blocks
    gemm_tpl<true><<<12 * S1 + 256, 256, 2 * (17408 + 33792)>>>(
        gos, INS, W1, INS, a1, HID, SPAN1, 12, 12 * S1, hpo);

    // fuse1 + cmax collapse (8) + acc2 zero (128)
    fuse1<<<FUSE1_BLKS + 8 + 128, 256>>>(b1, expx);

    // GEMM2 (A = fp16 g_xh): 416 single-chunk blocks
    gemm_tpl<false><<<16 * S2, 256, 2 * (9216 + 33792)>>>(
        xh, KXP, W2, KX, a2, NC, SPAN2, 16, 16 * S2, hpo);

    final_k<<<dim3(NC / 256, BB), 256>>>(b2, out);
}

// round 15
// speedup vs baseline: 1.1757x; 1.0131x over previous
#include <cuda_runtime.h>
#include <cuda_fp16.h>
#include <math.h>
#include <stdint.h>

#define BB    64
#define INS   10000
#define EXPS  53
#define HID   1500
#define NC    2048
#define KX    1553
#define KXP   1664
#define S1    18
#define SPAN1 568           // 18*568 = 10224 >= 10000, mult of 8
#define S2    9
#define SPAN2 192           // 9*192 = 1728 >= 1664, mult of 8

#define FUSE1_BLKS ((BB * KXP) / 256)   // 416

// ---------------- device scratch ----------------
__device__ float g_part1[S1][BB][HID];
__device__ __align__(16) float g_acc2[BB * NC];
__device__ __align__(16) __half g_xh[BB * KXP];
__device__ float g_cmax[32][NC];
__device__ float g_cmaxF[NC];

__device__ __forceinline__ uint32_t smem_u32(const void* p) {
    uint32_t a;
    asm("{ .reg .u64 t; cvta.to.shared.u64 t, %1; cvt.u32.u64 %0, t; }" : "=r"(a) : "l"(p));
    return a;
}
#define LDX4(r, addr)                                                        \
    asm volatile("ldmatrix.sync.aligned.m8n8.x4.shared.b16 {%0,%1,%2,%3}, [%4];" \
        : "=r"((r)[0]), "=r"((r)[1]), "=r"((r)[2]), "=r"((r)[3]) : "r"(addr))
#define LDX4T(r, addr)                                                       \
    asm volatile("ldmatrix.sync.aligned.m8n8.x4.trans.shared.b16 {%0,%1,%2,%3}, [%4];" \
        : "=r"((r)[0]), "=r"((r)[1]), "=r"((r)[2]), "=r"((r)[3]) : "r"(addr))
#define MMA16816(d, a, b)                                                    \
    asm volatile("mma.sync.aligned.m16n8k16.row.col.f32.f16.f16.f32 "       \
        "{%0,%1,%2,%3}, {%4,%5,%6,%7}, {%8,%9}, {%0,%1,%2,%3};"              \
        : "+f"((d)[0]), "+f"((d)[1]), "+f"((d)[2]), "+f"((d)[3])             \
        : "r"((a)[0]), "r"((a)[1]), "r"((a)[2]), "r"((a)[3]),                \
          "r"((b)[0]), "r"((b)[1]))
__device__ __forceinline__ void cp16(uint32_t dst, const void* src, int src_bytes) {
    asm volatile("cp.async.cg.shared.global [%0], [%1], 16, %2;"
                 :: "r"(dst), "l"(src), "r"(src_bytes) : "memory");
}
#define CP_COMMIT()  asm volatile("cp.async.commit_group;" ::: "memory")
#define CP_WAIT(n)   asm volatile("cp.async.wait_group %0;" :: "n"(n) : "memory")

// ---------------------------------------------------------------------------
// HMMA fp16 split-K GEMM, templated on A dtype and epilogue mode.
//   ATOMIC=0: store split-K partials (out + split*64*Nn).
//   ATOMIC=1: atomicAdd into accumulator (pre-zeroed).
// Blocks with flat id >= ngemm do hpo column-max strips (GEMM1 launch only).
// ---------------------------------------------------------------------------
template<bool AF32, bool ATOMIC>
__global__ __launch_bounds__(256, 2) void gemm_tpl(
    const void* __restrict__ Av, int KA,
    const float* __restrict__ W, int KB,
    float* __restrict__ outp, int Nn, int span,
    int nbx, int ngemm, const float* __restrict__ hpo)
{
    const int tid = threadIdx.x;
    const int bid = blockIdx.x;
    if (bid >= ngemm) {                        // fused hpo colmax strips
        int cb = bid - ngemm;                  // 0..255
        int strip = cb >> 3;
        int j = (cb & 7) * 256 + tid;
        const float* col = hpo + (size_t)(strip * 64) * NC + j;
        float m = col[0];
        #pragma unroll 8
        for (int i = 1; i < 64; i++)
            m = fmaxf(m, col[(size_t)i * NC]);
        g_cmax[strip][j] = m;
        return;
    }

    constexpr int OFF_B = AF32 ? 17408 : 9216;
    constexpr int STG   = OFF_B + 33792;

    extern __shared__ __align__(16) char sm[];
    const int lane = tid & 31, w = tid >> 5;
    const int n0 = (bid % nbx) * 128;
    const int k0 = (bid / nbx) * span;
    const int kendA = min(k0 + span, KA);
    const int kendB = min(k0 + span, KB);
    const int nch = (kendA - k0 + 63) >> 6;
    const uint32_t sbase = smem_u32(sm);
    const int wm = (w & 1) * 32, wn = (w >> 1) * 32;

    float acc[2][4][4];
    #pragma unroll
    for (int i = 0; i < 2; i++)
        #pragma unroll
        for (int j = 0; j < 4; j++)
            #pragma unroll
            for (int e = 0; e < 4; e++) acc[i][j][e] = 0.f;

    const int aRow = lane & 15, aCol2 = (lane >> 4) * 16;   // bytes
    const int bRowT = lane & 15, bColT = (lane >> 4) * 8;
    const int bSeg = (w >> 1) * 128;
    const int cvRow = (tid >> 5) * 8 + (tid & 7);
    const int cvSeg = (tid >> 3) & 3;

    auto stage_cp = [&](int c) {
        const int kt = k0 + c * 64;
        const uint32_t sb = sbase + (uint32_t)(c & 1) * STG;
        if (AF32) {
            #pragma unroll
            for (int u = 0; u < 4; u++) {      // A fp32: 1024 granules
                int i = tid + u * 256;
                int m = i >> 4, g = i & 15;
                int gk = kt + g * 4;
                const float* src = (const float*)Av + (size_t)m * KA + gk;
                int ok = (gk + 4 <= kendA) ? 16 : 0;
                cp16(sb + (uint32_t)(m * 272 + g * 16), src, ok);
            }
        } else {
            #pragma unroll
            for (int u = 0; u < 2; u++) {      // A fp16: 512 granules
                int i = tid + u * 256;
                int m = i >> 3, g = i & 7;
                int gk = kt + g * 8;
                const __half* src = (const __half*)Av + (size_t)m * KA + gk;
                int ok = (gk + 8 <= kendA) ? 16 : 0;
                cp16(sb + (uint32_t)(m * 144 + g * 16), src, ok);
            }
        }
        #pragma unroll
        for (int u = 0; u < 8; u++) {          // B fp32: 2048 granules
            int j = tid + u * 256;
            int r = j >> 5, g = j & 31;
            int gk = kt + r, n = n0 + g * 4;
            const float* src = W + (size_t)gk * Nn + n;
            int ok = (gk < kendB && n + 4 <= Nn) ? 16 : 0;
            cp16(sb + OFF_B + (uint32_t)(r * 528 + g * 16), src, ok);
        }
        CP_COMMIT();
    };

    stage_cp(0);

    for (int c = 0; c < nch; c++) {
        if (c + 1 < nch) { stage_cp(c + 1); CP_WAIT(1); }
        else             { CP_WAIT(0); }
        __syncthreads();

        {   // ---- in-place converts
            char* stg = sm + (c & 1) * STG;
            if (AF32) {
                char* pa = stg + (tid & 63) * 272 + (tid >> 6) * 64;
                float4 va[4];
                #pragma unroll
                for (int i = 0; i < 4; i++) va[i] = *(const float4*)(pa + i * 16);
                uint4 oa[2];
                #pragma unroll
                for (int i = 0; i < 2; i++) {
                    __half2 h0 = __floats2half2_rn(va[2*i].x,   va[2*i].y);
                    __half2 h1 = __floats2half2_rn(va[2*i].z,   va[2*i].w);
                    __half2 h2 = __floats2half2_rn(va[2*i+1].x, va[2*i+1].y);
                    __half2 h3 = __floats2half2_rn(va[2*i+1].z, va[2*i+1].w);
                    oa[i] = make_uint4(*(uint32_t*)&h0, *(uint32_t*)&h1,
                                       *(uint32_t*)&h2, *(uint32_t*)&h3);
                }
                *(uint4*)(pa)      = oa[0];
                *(uint4*)(pa + 16) = oa[1];
            }
            char* pr = stg + OFF_B + cvRow * 528 + cvSeg * 128;
            float4 v[8];
            #pragma unroll
            for (int i = 0; i < 8; i++) v[i] = *(const float4*)(pr + i * 16);
            uint4 o[4];
            #pragma unroll
            for (int i = 0; i < 4; i++) {
                __half2 h0 = __floats2half2_rn(v[2*i].x,   v[2*i].y);
                __half2 h1 = __floats2half2_rn(v[2*i].z,   v[2*i].w);
                __half2 h2 = __floats2half2_rn(v[2*i+1].x, v[2*i+1].y);
                __half2 h3 = __floats2half2_rn(v[2*i+1].z, v[2*i+1].w);
                o[i] = make_uint4(*(uint32_t*)&h0, *(uint32_t*)&h1,
                                  *(uint32_t*)&h2, *(uint32_t*)&h3);
            }
            #pragma unroll
            for (int i = 0; i < 4; i++)
                *(uint4*)(pr + i * 16) = o[i];
        }
        __syncthreads();

        const uint32_t sb = sbase + (uint32_t)(c & 1) * STG;
        #pragma unroll
        for (int ks = 0; ks < 4; ks++) {
            uint32_t af[2][4], bf[2][4];
            #pragma unroll
            for (int mi = 0; mi < 2; mi++) {
                uint32_t ad = AF32
                    ? sb + (wm + mi * 16 + aRow) * 272 + ks * 64 + aCol2
                    : sb + (wm + mi * 16 + aRow) * 144 + ks * 32 + aCol2;
                LDX4(af[mi], ad);
            }
            #pragma unroll
            for (int p = 0; p < 2; p++)
                LDX4T(bf[p], sb + OFF_B + (ks * 16 + bRowT) * 528 + bSeg
                             + (p * 16 + bColT) * 2);
            #pragma unroll
            for (int mi = 0; mi < 2; mi++)
                #pragma unroll
                for (int ni = 0; ni < 4; ni++)
                    MMA16816(acc[mi][ni], af[mi], (&bf[ni >> 1][(ni & 1) * 2]));
        }
        __syncthreads();
    }

    // ---- epilogue
    float* pb = ATOMIC ? outp : outp + (size_t)(bid / nbx) * 64 * Nn;
    #pragma unroll
    for (int mi = 0; mi < 2; mi++)
        #pragma unroll
        for (int ni = 0; ni < 4; ni++) {
            int r0 = wm + mi * 16 + (lane >> 2);
            int cc = n0 + wn + ni * 8 + (lane & 3) * 2;
            if (ATOMIC) {
                if (cc < Nn) {
                    atomicAdd(&pb[r0 * Nn + cc],       acc[mi][ni][0]);
                    atomicAdd(&pb[(r0 + 8) * Nn + cc], acc[mi][ni][2]);
                }
                if (cc + 1 < Nn) {
                    atomicAdd(&pb[r0 * Nn + cc + 1],       acc[mi][ni][1]);
                    atomicAdd(&pb[(r0 + 8) * Nn + cc + 1], acc[mi][ni][3]);
                }
            } else {
                if (cc < Nn) {
                    pb[r0 * Nn + cc] = acc[mi][ni][0];
                    pb[(r0 + 8) * Nn + cc] = acc[mi][ni][2];
                }
                if (cc + 1 < Nn) {
                    pb[r0 * Nn + cc + 1] = acc[mi][ni][1];
                    pb[(r0 + 8) * Nn + cc + 1] = acc[mi][ni][3];
                }
            }
        }
}

// ---- fuse1: partials + bias + GELU + concat -> fp16
//      tails: cmax 32->1 collapse (8 blocks), zero acc2 (128 blocks) --------
__global__ void fuse1(const float* __restrict__ b1, const float* __restrict__ expx)
{
    int bx = blockIdx.x;
    if (bx >= FUSE1_BLKS + 8) {                // zero acc2 before GEMM2
        int h = (bx - FUSE1_BLKS - 8) * 256 + threadIdx.x;
        *(float4*)&g_acc2[h * 4] = make_float4(0.f, 0.f, 0.f, 0.f);
        return;
    }
    if (bx >= FUSE1_BLKS) {                    // collapse cmax strips
        int j = (bx - FUSE1_BLKS) * 256 + threadIdx.x;   // 0..2047
        float m = g_cmax[0][j];
        #pragma unroll
        for (int p = 1; p < 32; p++) m = fmaxf(m, g_cmax[p][j]);
        g_cmaxF[j] = m;
        return;
    }
    int idx = bx * 256 + threadIdx.x;
    int b = idx / KXP, n = idx - b * KXP;
    float v;
    if (n < HID) {
        float s = b1[n];
        #pragma unroll
        for (int p = 0; p < S1; p++) s += g_part1[p][b][n];
        v = 0.5f * s * (1.f + erff(s * 0.70710678118654752f));
    } else if (n < KX) {
        v = expx[b * EXPS + (n - HID)];
    } else {
        v = 0.f;
    }
    g_xh[idx] = __float2half(v);
}

// ---- final: out[b,j] = sigmoid(acc2 + b2[j]) * cmaxF[j] (float4) ----------
__global__ void final_k(const float* __restrict__ b2, float* __restrict__ out)
{
    int g = blockIdx.x * 256 + threadIdx.x;    // 0..32767
    int b = g >> 9;
    int j4 = (g & 511) * 4;
    float4 m = *(const float4*)&g_cmaxF[j4];
    float4 s = *(const float4*)&b2[j4];
    float4 a = *(const float4*)&g_acc2[b * NC + j4];
    float4 o;
    o.x = m.x / (1.f + expf(-(s.x + a.x)));
    o.y = m.y / (1.f + expf(-(s.y + a.y)));
    o.z = m.z / (1.f + expf(-(s.z + a.z)));
    o.w = m.w / (1.f + expf(-(s.w + a.w)));
    *(float4*)&out[b * NC + j4] = o;
}

// ---------------- launcher ----------------
extern "C" void kernel_launch(void* const* d_in, const int* in_sizes, int n_in,
                              void* d_out, int out_size)
{
    const float* gos  = (const float*)d_in[0];
    const float* expx = (const float*)d_in[1];
    const float* W1   = (const float*)d_in[2];
    const float* b1   = (const float*)d_in[3];
    const float* W2   = (const float*)d_in[4];
    const float* b2   = (const float*)d_in[5];
    const float* hpo  = (const float*)d_in[6];
    float* out = (float*)d_out;

    cudaFuncSetAttribute((const void*)gemm_tpl<true, false>,
                         cudaFuncAttributeMaxDynamicSharedMemorySize, 102400);
    cudaFuncSetAttribute((const void*)gemm_tpl<false, true>,
                         cudaFuncAttributeMaxDynamicSharedMemorySize, 86016);

    __half* xh;
    float *p1, *a2;
    cudaGetSymbolAddress((void**)&xh, g_xh);
    cudaGetSymbolAddress((void**)&p1, g_part1);
    cudaGetSymbolAddress((void**)&a2, g_acc2);

    // GEMM1 (A = raw fp32 gos, partials epilogue) + fused hpo colmax strips
    gemm_tpl<true, false><<<12 * S1 + 256, 256, 102400>>>(
        gos, INS, W1, INS, p1, HID, SPAN1, 12, 12 * S1, hpo);

    // fuse1 + cmax collapse (8) + acc2 zero (128)
    fuse1<<<FUSE1_BLKS + 8 + 128, 256>>>(b1, expx);

    // GEMM2 (A = fp16 g_xh, atomic epilogue): 144 blocks, 3 chunks each
    gemm_tpl<false, true><<<16 * S2, 256, 86016>>>(
        xh, KXP, W2, KX, a2, NC, SPAN2, 16, 16 * S2, hpo);

    final_k<<<(BB * NC / 4) / 256, 256>>>(b2, out);
}